// round 10
// baseline (speedup 1.0000x reference)
#include <cuda_runtime.h>
#include <cstdint>

#define NRMAX   512
#define MAXPER  256            // bucket capacity per relation
#define TPB     128
#define HD      128
#define RD      64
#define WIN     16             // elements per window
#define SLICE   4112           // floats: src 2048 + skew 16 + dst 2048
#define DSTOFF  2064
#define GRID_C  304            // ~2 blocks/SM
#define NWARPS  (GRID_C * 4)

__device__ int g_cursor[NRMAX];              // zeroed by k_plan each run
__device__ int g_wcnt[NRMAX];
__device__ int g_win[NRMAX * (MAXPER / WIN)];
__device__ int g_total;
__device__ int g_perm[NRMAX * MAXPER];

// ---------- packed f32x2 helpers ----------
__device__ __forceinline__ unsigned long long pack2(float x, float y) {
    unsigned long long r;
    asm("mov.b64 %0, {%1, %2};" : "=l"(r) : "f"(x), "f"(y));
    return r;
}
__device__ __forceinline__ void ffma2(unsigned long long& d,
                                      unsigned long long a, unsigned long long b) {
    asm("fma.rn.f32x2 %0, %1, %2, %0;" : "+l"(d) : "l"(a), "l"(b));
}
__device__ __forceinline__ float2 unpack2(unsigned long long v) {
    float x, y;
    asm("mov.b64 {%0, %1}, %2;" : "=f"(x), "=f"(y) : "l"(v));
    return make_float2(x, y);
}

// ---------- pass 1: fused privatized scatter into fixed-stride buckets ----------
__global__ void k_scatter(const int* __restrict__ rel, int n) {
    __shared__ int s_cnt[NRMAX], s_base[NRMAX];
    for (int i = threadIdx.x; i < NRMAX; i += blockDim.x) s_cnt[i] = 0;
    __syncthreads();
    int base = blockIdx.x * blockDim.x * 4;
    int rl[4], lr[4];
    #pragma unroll
    for (int k = 0; k < 4; k++) {
        int i = base + k * blockDim.x + threadIdx.x;
        if (i < n) { rl[k] = rel[i]; lr[k] = atomicAdd(&s_cnt[rl[k]], 1); }
        else rl[k] = -1;
    }
    __syncthreads();
    for (int i = threadIdx.x; i < NRMAX; i += blockDim.x)
        if (s_cnt[i]) s_base[i] = atomicAdd(&g_cursor[i], s_cnt[i]);
    __syncthreads();
    #pragma unroll
    for (int k = 0; k < 4; k++) {
        int i = base + k * blockDim.x + threadIdx.x;
        if (rl[k] >= 0) {
            int p = s_base[rl[k]] + lr[k];
            if (p < MAXPER) g_perm[rl[k] * MAXPER + p] = i;
        }
    }
}

// ---------- pass 2: window plan (single block) + cursor reset ----------
__global__ void k_plan() {
    __shared__ int sc[NRMAX];
    int t = threadIdx.x;                        // 512 threads
    int c = g_cursor[t];
    if (c > MAXPER) c = MAXPER;
    g_wcnt[t]   = c;
    g_cursor[t] = 0;                            // reset for next replay
    int nw = (c + WIN - 1) >> 4;                // <= 16, so k fits in 4 bits
    sc[t] = nw; __syncthreads();
    for (int off = 1; off < NRMAX; off <<= 1) {
        int v = (t >= off) ? sc[t - off] : 0;
        __syncthreads();
        sc[t] += v;
        __syncthreads();
    }
    int base = sc[t] - nw;
    for (int k = 0; k < nw; k++) g_win[base + k] = (t << 4) | k;
    if (t == NRMAX - 1) g_total = sc[t];
}

// ---------- pass 3: compute — warp = one 16-element window, global pool ----------
// lane = (i4 = lane>>3 element-quad, j = lane&7 r-group); lane j owns
// r in {4j..4j+3} u {32+4j..32+4j+3}. Proj read directly from L1/L2.
__global__ __launch_bounds__(TPB) void k_compute(
    const int*   __restrict__ src,
    const int*   __restrict__ dst,
    const float* __restrict__ ent,
    const float* __restrict__ relemb,
    const float* __restrict__ proj,
    float*       __restrict__ out)
{
    extern __shared__ float smem[];
    int tid  = threadIdx.x;
    int lane = tid & 31;
    int warp = tid >> 5;
    float* slice = smem + warp * SLICE;

    int j  = lane & 7;
    int i4 = lane >> 3;
    unsigned gmask = 0xFFu << (lane & 24);

    int e   = lane >> 1;          // staging element (0..15)
    int sel = lane & 1;           // 0=src, 1=dst
    float* plane = slice + sel * DSTOFF;

    int total = g_total;
    int gwarp = blockIdx.x * 4 + warp;

    for (int wi = gwarp; wi < total; wi += NWARPS) {
        int wd   = g_win[wi];
        int r_id = wd >> 4;
        int k    = wd & 15;
        int cnt  = g_wcnt[r_id];
        const int* bucket = g_perm + r_id * MAXPER;

        __syncwarp();             // prior window's compute reads done

        int pos  = k * WIN + e;
        bool ok  = pos < cnt;
        int pidx = bucket[ok ? pos : (cnt - 1)];
        int my_oi = (ok && sel == 0) ? pidx : -1;
        int node = sel ? dst[pidx] : src[pidx];
        const float4* erow = (const float4*)(ent + (size_t)node * HD);

        // gather 128 h-values for this (element, sel): 32 LDG.128
        #pragma unroll
        for (int q = 0; q < 32; q++) {
            float4 v = erow[q];
            plane[(q * 4 + 0) * WIN + e] = v.x;
            plane[(q * 4 + 1) * WIN + e] = v.y;
            plane[(q * 4 + 2) * WIN + e] = v.z;
            plane[(q * 4 + 3) * WIN + e] = v.w;
        }
        __syncwarp();

        unsigned long long accS[4][4], accD[4][4];
        #pragma unroll
        for (int a = 0; a < 4; a++)
            #pragma unroll
            for (int p = 0; p < 4; p++) { accS[a][p] = 0ull; accD[a][p] = 0ull; }

        const float4* pbase = (const float4*)(proj + (size_t)r_id * (HD * RD));
        #pragma unroll 4
        for (int hl = 0; hl < HD; ++hl) {
            float4 Pa = __ldg(pbase + hl * 16 + j);
            float4 Pb = __ldg(pbase + hl * 16 + j + 8);
            unsigned long long PA0 = pack2(Pa.x, Pa.y);
            unsigned long long PA1 = pack2(Pa.z, Pa.w);
            unsigned long long PB0 = pack2(Pb.x, Pb.y);
            unsigned long long PB1 = pack2(Pb.z, Pb.w);
            float4 Sv = *(const float4*)(slice + hl * WIN + i4 * 4);
            float4 Dv = *(const float4*)(slice + DSTOFF + hl * WIN + i4 * 4);
            const float sv[4] = {Sv.x, Sv.y, Sv.z, Sv.w};
            const float dv[4] = {Dv.x, Dv.y, Dv.z, Dv.w};
            #pragma unroll
            for (int a = 0; a < 4; a++) {
                unsigned long long Se = pack2(sv[a], sv[a]);
                unsigned long long De = pack2(dv[a], dv[a]);
                ffma2(accS[a][0], Se, PA0);
                ffma2(accS[a][1], Se, PA1);
                ffma2(accS[a][2], Se, PB0);
                ffma2(accS[a][3], Se, PB1);
                ffma2(accD[a][0], De, PA0);
                ffma2(accD[a][1], De, PA1);
                ffma2(accD[a][2], De, PB0);
                ffma2(accD[a][3], De, PB1);
            }
        }

        // rel_emb for this lane's r-sets
        const float4* rrow = (const float4*)(relemb + (size_t)r_id * RD);
        float4 rva = __ldg(rrow + j);
        float4 rvb = __ldg(rrow + j + 8);
        const float rva_[4] = {rva.x, rva.y, rva.z, rva.w};
        const float rvb_[4] = {rvb.x, rvb.y, rvb.z, rvb.w};

        #pragma unroll
        for (int a = 0; a < 4; a++) {
            float s[8], d[8];
            #pragma unroll
            for (int p = 0; p < 4; p++) {
                float2 u = unpack2(accS[a][p]); s[2*p] = u.x; s[2*p+1] = u.y;
                float2 v = unpack2(accD[a][p]); d[2*p] = v.x; d[2*p+1] = v.y;
            }
            float ss = 0.f, dd = 0.f;
            #pragma unroll
            for (int kk = 0; kk < 8; kk++) { ss += s[kk]*s[kk]; dd += d[kk]*d[kk]; }
            #pragma unroll
            for (int o = 4; o > 0; o >>= 1) {
                ss += __shfl_xor_sync(gmask, ss, o);
                dd += __shfl_xor_sync(gmask, dd, o);
            }
            float inv_s = 1.f / fmaxf(sqrtf(ss), 1e-12f);
            float inv_d = 1.f / fmaxf(sqrtf(dd), 1e-12f);
            float rvk[8] = {rva_[0], rva_[1], rva_[2], rva_[3],
                            rvb_[0], rvb_[1], rvb_[2], rvb_[3]};
            float sc = 0.f;
            #pragma unroll
            for (int kk = 0; kk < 8; kk++) {
                float df = s[kk] * inv_s + rvk[kk] - d[kk] * inv_d;
                sc += df * df;
            }
            #pragma unroll
            for (int o = 4; o > 0; o >>= 1) sc += __shfl_xor_sync(gmask, sc, o);
            // output index lives in lane 2*(i4*4+a) (sel==0 staging lane)
            int oi = __shfl_sync(0xFFFFFFFFu, my_oi, (i4 * 4 + a) << 1);
            if (j == 0 && oi >= 0) out[oi] = sqrtf(sc);
        }
    }
}

// ---------- launch ----------
extern "C" void kernel_launch(void* const* d_in, const int* in_sizes, int n_in,
                              void* d_out, int out_size) {
    const int*   src = (const int*)d_in[0];
    const int*   rel = (const int*)d_in[1];
    const int*   dst = (const int*)d_in[2];
    const float* ent = (const float*)d_in[3];
    const float* rle = (const float*)d_in[4];
    const float* prj = (const float*)d_in[5];
    float*       out = (float*)d_out;

    int B = in_sizes[0];

    const int SMEM_BYTES = 4 * SLICE * 4;     // 65792 B (4 warp slices)
    cudaFuncSetAttribute(k_compute, cudaFuncAttributeMaxDynamicSharedMemorySize,
                         SMEM_BYTES);

    int gS = (B + 256 * 4 - 1) / (256 * 4);   // 64 blocks

    k_scatter<<<gS, 256>>>(rel, B);
    k_plan<<<1, NRMAX>>>();
    k_compute<<<GRID_C, TPB, SMEM_BYTES>>>(src, dst, ent, rle, prj, out);
}

// round 11
// speedup vs baseline: 1.5290x; 1.5290x over previous
#include <cuda_runtime.h>
#include <cstdint>

#define NRMAX   512
#define MAXPER  256            // bucket capacity per relation
#define TPB     128
#define WPB     4
#define HD      128
#define RD      64
#define WIN     16             // elements per warp-window
#define SLICE   4112           // floats: src 2048 + skew 16 + dst 2048
#define DSTOFF  2064
#define GRID_C  304

__device__ int g_cursor[NRMAX];              // zeroed by k_plan for next replay
__device__ int g_wcnt[NRMAX];
__device__ int g_order[NRMAX];               // relations sorted by count desc
__device__ int g_next;                       // queue head (reset by k_plan)
__device__ int g_perm[NRMAX * MAXPER];

// ---------- packed f32x2 helpers ----------
__device__ __forceinline__ unsigned long long pack2(float x, float y) {
    unsigned long long r;
    asm("mov.b64 %0, {%1, %2};" : "=l"(r) : "f"(x), "f"(y));
    return r;
}
__device__ __forceinline__ void ffma2(unsigned long long& d,
                                      unsigned long long a, unsigned long long b) {
    asm("fma.rn.f32x2 %0, %1, %2, %0;" : "+l"(d) : "l"(a), "l"(b));
}
__device__ __forceinline__ float2 unpack2(unsigned long long v) {
    float x, y;
    asm("mov.b64 {%0, %1}, %2;" : "=f"(x), "=f"(y) : "l"(v));
    return make_float2(x, y);
}

// ---------- pass 1: fused privatized scatter into fixed-stride buckets ----------
__global__ void k_scatter(const int* __restrict__ rel, int n) {
    __shared__ int s_cnt[NRMAX], s_base[NRMAX];
    for (int i = threadIdx.x; i < NRMAX; i += blockDim.x) s_cnt[i] = 0;
    __syncthreads();
    int base = blockIdx.x * blockDim.x * 4;
    int rl[4], lr[4];
    #pragma unroll
    for (int k = 0; k < 4; k++) {
        int i = base + k * blockDim.x + threadIdx.x;
        if (i < n) { rl[k] = rel[i]; lr[k] = atomicAdd(&s_cnt[rl[k]], 1); }
        else rl[k] = -1;
    }
    __syncthreads();
    for (int i = threadIdx.x; i < NRMAX; i += blockDim.x)
        if (s_cnt[i]) s_base[i] = atomicAdd(&g_cursor[i], s_cnt[i]);
    __syncthreads();
    #pragma unroll
    for (int k = 0; k < 4; k++) {
        int i = base + k * blockDim.x + threadIdx.x;
        if (rl[k] >= 0) {
            int p = s_base[rl[k]] + lr[k];
            if (p < MAXPER) g_perm[rl[k] * MAXPER + p] = i;
        }
    }
}

// ---------- pass 2: plan — counts, descending sort, resets (single block) ----------
__global__ void k_plan() {
    __shared__ int s_c[NRMAX];
    int t = threadIdx.x;                      // 512 threads
    int c = g_cursor[t];
    if (c > MAXPER) c = MAXPER;
    g_wcnt[t]   = c;
    g_cursor[t] = 0;                          // reset for next replay
    if (t == 0) g_next = 0;                   // reset queue head
    s_c[t] = c;
    __syncthreads();
    // rank by count descending (stable by index)
    int rank = 0;
    for (int i = 0; i < NRMAX; i++) {
        int ci = s_c[i];
        rank += (ci > c) || (ci == c && i < t);
    }
    g_order[rank] = t;
}

// ---------- pass 3: compute — persistent blocks pull relations off queue ----------
// lane = (i4 = lane>>3 element-quad, j = lane&7 r-group); lane j owns
// r in {4j..4j+3} u {32+4j..32+4j+3}. Full-h staging: one gather per window.
__global__ __launch_bounds__(TPB, 2) void k_compute(
    const int*   __restrict__ src,
    const int*   __restrict__ dst,
    const float* __restrict__ ent,
    const float* __restrict__ relemb,
    const float* __restrict__ proj,
    float*       __restrict__ out)
{
    extern __shared__ float smem[];
    float* s_proj = smem;                     // 8192 floats (proj [h][r])
    float* s_emb  = smem + HD * RD;           // WPB * SLICE
    __shared__ int s_wi[WPB][WIN];
    __shared__ int s_rid;

    int tid  = threadIdx.x;
    int lane = tid & 31;
    int warp = tid >> 5;
    int j  = lane & 7;
    int i4 = lane >> 3;
    unsigned gmask = 0xFFu << (lane & 24);

    float* slice = s_emb + warp * SLICE;
    int e   = lane >> 1;          // staging element (0..15)
    int sel = lane & 1;           // 0=src, 1=dst
    float* plane = slice + sel * DSTOFF;

    for (;;) {
        if (tid == 0) s_rid = atomicAdd(&g_next, 1);
        __syncthreads();
        int idx = s_rid;
        if (idx >= NRMAX) break;              // uniform exit
        int r_id = g_order[idx];
        int cnt  = g_wcnt[r_id];

        if (cnt > 0) {
            // stage proj (row-major [h][r])
            const float4* p4 = (const float4*)(proj + (size_t)r_id * (HD * RD));
            float4* sp4 = (float4*)s_proj;
            #pragma unroll
            for (int t2 = tid; t2 < HD * RD / 4; t2 += TPB) sp4[t2] = p4[t2];
            __syncthreads();

            const float4* rrow = (const float4*)(relemb + (size_t)r_id * RD);
            float4 rva = rrow[j];
            float4 rvb = rrow[j + 8];
            const int* bucket = g_perm + r_id * MAXPER;

            int nwin = (cnt + WIN - 1) >> 4;
            for (int w = warp; w < nwin; w += WPB) {
                __syncwarp();     // prior epilogue reads done before overwrite

                int pos  = w * WIN + e;
                bool ok  = pos < cnt;
                int pidx = bucket[ok ? pos : (cnt - 1)];
                if (sel == 0) s_wi[warp][e] = ok ? pidx : -1;
                int node = sel ? dst[pidx] : src[pidx];
                const float4* erow = (const float4*)(ent + (size_t)node * HD);

                // gather all 128 h-values for this (element, sel): 32 LDG.128
                #pragma unroll
                for (int q = 0; q < 32; q++) {
                    float4 v = erow[q];
                    plane[(q * 4 + 0) * WIN + e] = v.x;
                    plane[(q * 4 + 1) * WIN + e] = v.y;
                    plane[(q * 4 + 2) * WIN + e] = v.z;
                    plane[(q * 4 + 3) * WIN + e] = v.w;
                }
                __syncwarp();

                unsigned long long accS[4][4], accD[4][4];
                #pragma unroll
                for (int a = 0; a < 4; a++)
                    #pragma unroll
                    for (int p = 0; p < 4; p++) { accS[a][p] = 0ull; accD[a][p] = 0ull; }

                const float4* pp = (const float4*)s_proj;
                #pragma unroll 4
                for (int hl = 0; hl < HD; ++hl) {
                    float4 Pa = pp[hl * 16 + j];
                    float4 Pb = pp[hl * 16 + j + 8];
                    unsigned long long PA0 = pack2(Pa.x, Pa.y);
                    unsigned long long PA1 = pack2(Pa.z, Pa.w);
                    unsigned long long PB0 = pack2(Pb.x, Pb.y);
                    unsigned long long PB1 = pack2(Pb.z, Pb.w);
                    float4 Sv = *(const float4*)(slice + hl * WIN + i4 * 4);
                    float4 Dv = *(const float4*)(slice + DSTOFF + hl * WIN + i4 * 4);
                    const float sv[4] = {Sv.x, Sv.y, Sv.z, Sv.w};
                    const float dv[4] = {Dv.x, Dv.y, Dv.z, Dv.w};
                    #pragma unroll
                    for (int a = 0; a < 4; a++) {
                        unsigned long long Se = pack2(sv[a], sv[a]);
                        unsigned long long De = pack2(dv[a], dv[a]);
                        ffma2(accS[a][0], Se, PA0);
                        ffma2(accS[a][1], Se, PA1);
                        ffma2(accS[a][2], Se, PB0);
                        ffma2(accS[a][3], Se, PB1);
                        ffma2(accD[a][0], De, PA0);
                        ffma2(accD[a][1], De, PA1);
                        ffma2(accD[a][2], De, PB0);
                        ffma2(accD[a][3], De, PB1);
                    }
                }

                // epilogue
                const float rva_[4] = {rva.x, rva.y, rva.z, rva.w};
                const float rvb_[4] = {rvb.x, rvb.y, rvb.z, rvb.w};
                #pragma unroll
                for (int a = 0; a < 4; a++) {
                    float s[8], d[8];
                    #pragma unroll
                    for (int p = 0; p < 4; p++) {
                        float2 u = unpack2(accS[a][p]); s[2*p] = u.x; s[2*p+1] = u.y;
                        float2 v = unpack2(accD[a][p]); d[2*p] = v.x; d[2*p+1] = v.y;
                    }
                    float ss = 0.f, dd = 0.f;
                    #pragma unroll
                    for (int k = 0; k < 8; k++) { ss += s[k]*s[k]; dd += d[k]*d[k]; }
                    #pragma unroll
                    for (int o = 4; o > 0; o >>= 1) {
                        ss += __shfl_xor_sync(gmask, ss, o);
                        dd += __shfl_xor_sync(gmask, dd, o);
                    }
                    float inv_s = 1.f / fmaxf(sqrtf(ss), 1e-12f);
                    float inv_d = 1.f / fmaxf(sqrtf(dd), 1e-12f);
                    float rvk[8] = {rva_[0], rva_[1], rva_[2], rva_[3],
                                    rvb_[0], rvb_[1], rvb_[2], rvb_[3]};
                    float sc = 0.f;
                    #pragma unroll
                    for (int k = 0; k < 8; k++) {
                        float df = s[k] * inv_s + rvk[k] - d[k] * inv_d;
                        sc += df * df;
                    }
                    #pragma unroll
                    for (int o = 4; o > 0; o >>= 1) sc += __shfl_xor_sync(gmask, sc, o);
                    if (j == 0) {
                        int oi = s_wi[warp][i4 * 4 + a];
                        if (oi >= 0) out[oi] = sqrtf(sc);
                    }
                }
            }
        }
        __syncthreads();          // all warps done before s_rid/proj reuse
    }
}

// ---------- launch ----------
extern "C" void kernel_launch(void* const* d_in, const int* in_sizes, int n_in,
                              void* d_out, int out_size) {
    const int*   src = (const int*)d_in[0];
    const int*   rel = (const int*)d_in[1];
    const int*   dst = (const int*)d_in[2];
    const float* ent = (const float*)d_in[3];
    const float* rle = (const float*)d_in[4];
    const float* prj = (const float*)d_in[5];
    float*       out = (float*)d_out;

    int B = in_sizes[0];

    const int SMEM_BYTES = (HD * RD + WPB * SLICE) * 4;   // 98560
    cudaFuncSetAttribute(k_compute, cudaFuncAttributeMaxDynamicSharedMemorySize,
                         SMEM_BYTES);

    int gS = (B + 256 * 4 - 1) / (256 * 4);   // 64 blocks

    k_scatter<<<gS, 256>>>(rel, B);
    k_plan<<<1, NRMAX>>>();
    k_compute<<<GRID_C, TPB, SMEM_BYTES>>>(src, dst, ent, rle, prj, out);
}

// round 12
// speedup vs baseline: 1.5662x; 1.0243x over previous
#include <cuda_runtime.h>
#include <cstdint>

#define NRMAX   512
#define MAXPER  256
#define TPB     128
#define WPB     4
#define HD      128
#define RD      64
#define WIN     8              // elements per warp-window
#define RSTRIDE 132            // floats per emb row (128 + pad)
#define BUFFL   (16 * RSTRIDE) // floats per buffer (16 rows: 8 src + 8 dst)
#define GRID_C  304

__device__ int g_cursor[NRMAX];
__device__ int g_wcnt[NRMAX];
__device__ int g_order[NRMAX];
__device__ int g_next;
__device__ int g_perm[NRMAX * MAXPER];

// ---------- helpers ----------
__device__ __forceinline__ unsigned long long pack2(float x, float y) {
    unsigned long long r;
    asm("mov.b64 %0, {%1, %2};" : "=l"(r) : "f"(x), "f"(y));
    return r;
}
__device__ __forceinline__ void ffma2(unsigned long long& d,
                                      unsigned long long a, unsigned long long b) {
    asm("fma.rn.f32x2 %0, %1, %2, %0;" : "+l"(d) : "l"(a), "l"(b));
}
__device__ __forceinline__ float2 unpack2(unsigned long long v) {
    float x, y;
    asm("mov.b64 {%0, %1}, %2;" : "=f"(x), "=f"(y) : "l"(v));
    return make_float2(x, y);
}
__device__ __forceinline__ uint32_t smem_u32(const void* p) {
    uint32_t a;
    asm("{ .reg .u64 t; cvta.to.shared.u64 t, %1; cvt.u32.u64 %0, t; }"
        : "=r"(a) : "l"(p));
    return a;
}
__device__ __forceinline__ void cp_async16(uint32_t s, const void* g) {
    asm volatile("cp.async.cg.shared.global [%0], [%1], 16;" :: "r"(s), "l"(g));
}
#define CP_COMMIT() asm volatile("cp.async.commit_group;" ::: "memory")
#define CP_WAIT(n)  asm volatile("cp.async.wait_group %0;" :: "n"(n) : "memory")

// ---------- pass 1: fused privatized scatter ----------
__global__ void k_scatter(const int* __restrict__ rel, int n) {
    __shared__ int s_cnt[NRMAX], s_base[NRMAX];
    for (int i = threadIdx.x; i < NRMAX; i += blockDim.x) s_cnt[i] = 0;
    __syncthreads();
    int base = blockIdx.x * blockDim.x * 4;
    int rl[4], lr[4];
    #pragma unroll
    for (int k = 0; k < 4; k++) {
        int i = base + k * blockDim.x + threadIdx.x;
        if (i < n) { rl[k] = rel[i]; lr[k] = atomicAdd(&s_cnt[rl[k]], 1); }
        else rl[k] = -1;
    }
    __syncthreads();
    for (int i = threadIdx.x; i < NRMAX; i += blockDim.x)
        if (s_cnt[i]) s_base[i] = atomicAdd(&g_cursor[i], s_cnt[i]);
    __syncthreads();
    #pragma unroll
    for (int k = 0; k < 4; k++) {
        int i = base + k * blockDim.x + threadIdx.x;
        if (rl[k] >= 0) {
            int p = s_base[rl[k]] + lr[k];
            if (p < MAXPER) g_perm[rl[k] * MAXPER + p] = i;
        }
    }
}

// ---------- pass 2: plan — counts, descending rank, resets ----------
__global__ void k_plan() {
    __shared__ int s_c[NRMAX];
    int t = threadIdx.x;
    int c = g_cursor[t];
    if (c > MAXPER) c = MAXPER;
    g_wcnt[t]   = c;
    g_cursor[t] = 0;
    if (t == 0) g_next = 0;
    s_c[t] = c;
    __syncthreads();
    int rank = 0;
    for (int i = 0; i < NRMAX; i++) {
        int ci = s_c[i];
        rank += (ci > c) || (ci == c && i < t);
    }
    g_order[rank] = t;
}

// ---------- pass 3: compute — persistent queue, cp.async-pipelined windows --
// warp-window WIN=8: lane=(i4=lane>>3 elem-quad2, j=lane&7 r-group).
// lane j owns r {4j..4j+3} u {32+4j..32+4j+3}; each lane 2 elements.
__global__ __launch_bounds__(TPB, 2) void k_compute(
    const int*   __restrict__ src,
    const int*   __restrict__ dst,
    const float* __restrict__ ent,
    const float* __restrict__ relemb,
    const float* __restrict__ proj,
    float*       __restrict__ out)
{
    extern __shared__ float smem[];
    float* s_proj = smem;                     // 8192 floats
    float* s_emb  = smem + HD * RD;           // WPB * 2 * BUFFL floats
    __shared__ int s_wi[WPB][2][WIN];
    __shared__ int s_rid;

    int tid  = threadIdx.x;
    int lane = tid & 31;
    int warp = tid >> 5;
    int j    = lane & 7;
    int i4   = lane >> 3;
    unsigned gmask = 0xFFu << (lane & 24);

    // staging role: e = lane&7, sel = (lane>>3)&1, half = lane>>4
    int e_st   = lane & 7;
    int sel_st = (lane >> 3) & 1;
    int half   = lane >> 4;

    uint32_t emb_u32 = smem_u32(s_emb);
    float* mybuf0 = s_emb + (warp * 2) * BUFFL;

    for (;;) {
        if (tid == 0) s_rid = atomicAdd(&g_next, 1);
        __syncthreads();
        int idx = s_rid;
        if (idx >= NRMAX) break;
        int r_id = g_order[idx];
        int cnt  = g_wcnt[r_id];

        if (cnt > 0) {
            const float4* p4 = (const float4*)(proj + (size_t)r_id * (HD * RD));
            float4* sp4 = (float4*)s_proj;
            #pragma unroll
            for (int t2 = tid; t2 < HD * RD / 4; t2 += TPB) sp4[t2] = p4[t2];
            __syncthreads();

            const float4* rrow = (const float4*)(relemb + (size_t)r_id * RD);
            float4 rva = rrow[j];
            float4 rvb = rrow[j + 8];
            const float rva_[4] = {rva.x, rva.y, rva.z, rva.w};
            const float rvb_[4] = {rvb.x, rvb.y, rvb.z, rvb.w};
            const int* bucket = g_perm + r_id * MAXPER;

            int nwin = (cnt + WIN - 1) >> 3;

            // stage(w, b): issue 16 cp.async for this lane's half-row
            auto stage = [&](int w, int b) {
                int pos  = w * WIN + e_st;
                bool ok  = pos < cnt;
                int pidx = bucket[ok ? pos : (cnt - 1)];
                if (sel_st == 0 && half == 0) s_wi[warp][b][e_st] = ok ? pidx : -1;
                int node = sel_st ? dst[pidx] : src[pidx];
                const float4* erow = (const float4*)(ent + (size_t)node * HD);
                uint32_t d32 = emb_u32 +
                    (((warp * 2 + b) * BUFFL +
                      (sel_st * 8 + e_st) * RSTRIDE + half * 64) << 2);
                #pragma unroll
                for (int q = 0; q < 16; q++)
                    cp_async16(d32 + q * 16, erow + half * 16 + q);
                CP_COMMIT();
            };

            int b = 0;
            if (warp < nwin) stage(warp, 0);

            for (int w = warp; w < nwin; w += WPB) {
                int wn = w + WPB;
                if (wn < nwin) { stage(wn, b ^ 1); CP_WAIT(1); }
                else           { CP_WAIT(0); }
                __syncwarp();

                const float* buf = mybuf0 + b * BUFFL;
                unsigned long long accS[2][4], accD[2][4];
                #pragma unroll
                for (int a = 0; a < 2; a++)
                    #pragma unroll
                    for (int p = 0; p < 4; p++) { accS[a][p] = 0ull; accD[a][p] = 0ull; }

                const float4* pp = (const float4*)s_proj;
                const float* sr0 = buf + (i4 * 2) * RSTRIDE;
                const float* sr1 = buf + (i4 * 2 + 1) * RSTRIDE;
                const float* dr0 = sr0 + 8 * RSTRIDE;
                const float* dr1 = sr1 + 8 * RSTRIDE;

                #pragma unroll 4
                for (int hl = 0; hl < HD; ++hl) {
                    float4 Pa = pp[hl * 16 + j];
                    float4 Pb = pp[hl * 16 + j + 8];
                    unsigned long long PA0 = pack2(Pa.x, Pa.y);
                    unsigned long long PA1 = pack2(Pa.z, Pa.w);
                    unsigned long long PB0 = pack2(Pb.x, Pb.y);
                    unsigned long long PB1 = pack2(Pb.z, Pb.w);
                    float sv0 = sr0[hl], sv1 = sr1[hl];
                    float dv0 = dr0[hl], dv1 = dr1[hl];
                    unsigned long long S0 = pack2(sv0, sv0);
                    unsigned long long S1 = pack2(sv1, sv1);
                    unsigned long long D0 = pack2(dv0, dv0);
                    unsigned long long D1 = pack2(dv1, dv1);
                    ffma2(accS[0][0], S0, PA0); ffma2(accS[0][1], S0, PA1);
                    ffma2(accS[0][2], S0, PB0); ffma2(accS[0][3], S0, PB1);
                    ffma2(accS[1][0], S1, PA0); ffma2(accS[1][1], S1, PA1);
                    ffma2(accS[1][2], S1, PB0); ffma2(accS[1][3], S1, PB1);
                    ffma2(accD[0][0], D0, PA0); ffma2(accD[0][1], D0, PA1);
                    ffma2(accD[0][2], D0, PB0); ffma2(accD[0][3], D0, PB1);
                    ffma2(accD[1][0], D1, PA0); ffma2(accD[1][1], D1, PA1);
                    ffma2(accD[1][2], D1, PB0); ffma2(accD[1][3], D1, PB1);
                }

                #pragma unroll
                for (int a = 0; a < 2; a++) {
                    float s[8], d[8];
                    #pragma unroll
                    for (int p = 0; p < 4; p++) {
                        float2 u = unpack2(accS[a][p]); s[2*p] = u.x; s[2*p+1] = u.y;
                        float2 v = unpack2(accD[a][p]); d[2*p] = v.x; d[2*p+1] = v.y;
                    }
                    float ss = 0.f, dd = 0.f;
                    #pragma unroll
                    for (int k = 0; k < 8; k++) { ss += s[k]*s[k]; dd += d[k]*d[k]; }
                    #pragma unroll
                    for (int o = 4; o > 0; o >>= 1) {
                        ss += __shfl_xor_sync(gmask, ss, o);
                        dd += __shfl_xor_sync(gmask, dd, o);
                    }
                    float inv_s = 1.f / fmaxf(sqrtf(ss), 1e-12f);
                    float inv_d = 1.f / fmaxf(sqrtf(dd), 1e-12f);
                    float rvk[8] = {rva_[0], rva_[1], rva_[2], rva_[3],
                                    rvb_[0], rvb_[1], rvb_[2], rvb_[3]};
                    float sc = 0.f;
                    #pragma unroll
                    for (int k = 0; k < 8; k++) {
                        float df = s[k] * inv_s + rvk[k] - d[k] * inv_d;
                        sc += df * df;
                    }
                    #pragma unroll
                    for (int o = 4; o > 0; o >>= 1) sc += __shfl_xor_sync(gmask, sc, o);
                    if (j == 0) {
                        int oi = s_wi[warp][b][i4 * 2 + a];
                        if (oi >= 0) out[oi] = sqrtf(sc);
                    }
                }
                b ^= 1;
            }
        }
        __syncthreads();
    }
}

// ---------- launch ----------
extern "C" void kernel_launch(void* const* d_in, const int* in_sizes, int n_in,
                              void* d_out, int out_size) {
    const int*   src = (const int*)d_in[0];
    const int*   rel = (const int*)d_in[1];
    const int*   dst = (const int*)d_in[2];
    const float* ent = (const float*)d_in[3];
    const float* rle = (const float*)d_in[4];
    const float* prj = (const float*)d_in[5];
    float*       out = (float*)d_out;

    int B = in_sizes[0];

    const int SMEM_BYTES = (HD * RD + WPB * 2 * BUFFL) * 4;  // 32768+67584=100352
    cudaFuncSetAttribute(k_compute, cudaFuncAttributeMaxDynamicSharedMemorySize,
                         SMEM_BYTES);

    int gS = (B + 256 * 4 - 1) / (256 * 4);   // 64 blocks

    k_scatter<<<gS, 256>>>(rel, B);
    k_plan<<<1, NRMAX>>>();
    k_compute<<<GRID_C, TPB, SMEM_BYTES>>>(src, dst, ent, rle, prj, out);
}

// round 13
// speedup vs baseline: 2.2461x; 1.4341x over previous
#include <cuda_runtime.h>
#include <cstdint>

#define NRMAX   512
#define MAXPER  256
#define TPB     128
#define WPB     4
#define HD      128
#define RD      64
#define WIN     8              // elements per warp-window (16 A-rows: 8 src + 8 dst)
#define RSTRIDE 132            // floats per A row (128 + pad -> banks 4g+t)
#define BUFFL   (16 * RSTRIDE) // floats per A buffer (16 rows)
#define BFRAGS  8192           // B-fragment pool (tf32 bits), 32 KB
#define GRID_C  304

__device__ int g_cursor[NRMAX];
__device__ int g_wcnt[NRMAX];
__device__ int g_order[NRMAX];
__device__ int g_next;
__device__ int g_perm[NRMAX * MAXPER];

// ---------- helpers ----------
__device__ __forceinline__ uint32_t smem_u32(const void* p) {
    uint32_t a;
    asm("{ .reg .u64 t; cvta.to.shared.u64 t, %1; cvt.u32.u64 %0, t; }"
        : "=r"(a) : "l"(p));
    return a;
}
__device__ __forceinline__ void cp_async16(uint32_t s, const void* g) {
    asm volatile("cp.async.cg.shared.global [%0], [%1], 16;" :: "r"(s), "l"(g));
}
#define CP_COMMIT() asm volatile("cp.async.commit_group;" ::: "memory")
#define CP_WAIT(n)  asm volatile("cp.async.wait_group %0;" :: "n"(n) : "memory")

__device__ __forceinline__ uint32_t f2tf32(float f) {
    uint32_t u;
    asm("cvt.rna.tf32.f32 %0, %1;" : "=r"(u) : "f"(f));
    return u;
}
__device__ __forceinline__ void mma_tf32(float c[4], uint32_t a0, uint32_t a1,
                                         uint32_t a2, uint32_t a3,
                                         uint32_t b0, uint32_t b1) {
    asm volatile(
        "mma.sync.aligned.m16n8k8.row.col.f32.tf32.tf32.f32 "
        "{%0,%1,%2,%3}, {%4,%5,%6,%7}, {%8,%9}, {%0,%1,%2,%3};"
        : "+f"(c[0]), "+f"(c[1]), "+f"(c[2]), "+f"(c[3])
        : "r"(a0), "r"(a1), "r"(a2), "r"(a3), "r"(b0), "r"(b1));
}

// ---------- pass 1: fused privatized scatter ----------
__global__ void k_scatter(const int* __restrict__ rel, int n) {
    __shared__ int s_cnt[NRMAX], s_base[NRMAX];
    for (int i = threadIdx.x; i < NRMAX; i += blockDim.x) s_cnt[i] = 0;
    __syncthreads();
    int base = blockIdx.x * blockDim.x * 4;
    int rl[4], lr[4];
    #pragma unroll
    for (int k = 0; k < 4; k++) {
        int i = base + k * blockDim.x + threadIdx.x;
        if (i < n) { rl[k] = rel[i]; lr[k] = atomicAdd(&s_cnt[rl[k]], 1); }
        else rl[k] = -1;
    }
    __syncthreads();
    for (int i = threadIdx.x; i < NRMAX; i += blockDim.x)
        if (s_cnt[i]) s_base[i] = atomicAdd(&g_cursor[i], s_cnt[i]);
    __syncthreads();
    #pragma unroll
    for (int k = 0; k < 4; k++) {
        int i = base + k * blockDim.x + threadIdx.x;
        if (rl[k] >= 0) {
            int p = s_base[rl[k]] + lr[k];
            if (p < MAXPER) g_perm[rl[k] * MAXPER + p] = i;
        }
    }
}

// ---------- pass 2: plan — counts, descending rank, resets ----------
__global__ void k_plan() {
    __shared__ int s_c[NRMAX];
    int t = threadIdx.x;
    int c = g_cursor[t];
    if (c > MAXPER) c = MAXPER;
    g_wcnt[t]   = c;
    g_cursor[t] = 0;
    if (t == 0) g_next = 0;
    s_c[t] = c;
    __syncthreads();
    int rank = 0;
    for (int i = 0; i < NRMAX; i++) {
        int ci = s_c[i];
        rank += (ci > c) || (ci == c && i < t);
    }
    g_order[rank] = t;
}

// ---------- pass 3: compute — tf32 mma windows, persistent sorted queue ----
// warp-window of 8 elements -> A[16x128] (rows 0-7 src, 8-15 dst).
// lane: g = lane>>2 (row/element), t = lane&3.
__global__ __launch_bounds__(TPB, 2) void k_compute(
    const int*   __restrict__ src,
    const int*   __restrict__ dst,
    const float* __restrict__ ent,
    const float* __restrict__ relemb,
    const float* __restrict__ proj,
    float*       __restrict__ out)
{
    extern __shared__ float smem[];
    uint32_t* s_bf  = (uint32_t*)smem;        // BFRAGS tf32 B fragments
    float*    s_emb = smem + BFRAGS;          // WPB * 2 * BUFFL floats
    __shared__ int s_wi[WPB][2][WIN];
    __shared__ int s_rid;

    int tid  = threadIdx.x;
    int lane = tid & 31;
    int warp = tid >> 5;
    int g    = lane >> 2;
    int t4   = lane & 3;
    unsigned qmask = 0xFu << (lane & 28);     // quad sharing element g

    // staging role: row = lane>>1 (0..15), half = lane&1
    int row_st  = lane >> 1;
    int half_st = lane & 1;
    int e_st    = row_st & 7;
    int sel_st  = row_st >> 3;

    uint32_t emb_u32 = smem_u32(s_emb);
    float* mybuf0 = s_emb + (warp * 2) * BUFFL;

    for (;;) {
        if (tid == 0) s_rid = atomicAdd(&g_next, 1);
        __syncthreads();
        int idx = s_rid;
        if (idx >= NRMAX) break;
        int r_id = g_order[idx];
        int cnt  = g_wcnt[r_id];

        if (cnt > 0) {
            // stage proj into B-fragment layout (tf32 bits):
            // F(h,r) = (h>>3)*512 + (r>>3)*64 + ((r&7)*4 + (h&3))*2 + ((h>>2)&1)
            {
                const float4* p4 = (const float4*)(proj + (size_t)r_id * (HD * RD));
                for (int i = tid; i < HD * RD / 4; i += TPB) {
                    float4 v = p4[i];
                    int h  = i >> 4;
                    int r0 = (i & 15) * 4;
                    int hb = (h >> 3) * 512 + ((h & 3) * 2) + ((h >> 2) & 1);
                    float vv[4] = {v.x, v.y, v.z, v.w};
                    #pragma unroll
                    for (int m = 0; m < 4; m++) {
                        int r = r0 + m;
                        s_bf[hb + (r >> 3) * 64 + (r & 7) * 8] = f2tf32(vv[m]);
                    }
                }
            }
            __syncthreads();

            // rel_emb per lane: cols nt*8 + 2*t4 (+1)
            const float2* rr2 = (const float2*)(relemb + (size_t)r_id * RD);
            float2 rv[8];
            #pragma unroll
            for (int nt = 0; nt < 8; nt++) rv[nt] = rr2[nt * 4 + t4];

            const int* bucket = g_perm + r_id * MAXPER;
            int nwin = (cnt + WIN - 1) >> 3;

            auto stage = [&](int w, int b) {
                int pos  = w * WIN + e_st;
                bool ok  = pos < cnt;
                int pidx = bucket[ok ? pos : (cnt - 1)];
                if (sel_st == 0 && half_st == 0)
                    s_wi[warp][b][e_st] = ok ? pidx : -1;
                int node = sel_st ? dst[pidx] : src[pidx];
                const float4* erow = (const float4*)(ent + (size_t)node * HD);
                uint32_t d32 = emb_u32 +
                    (((warp * 2 + b) * BUFFL + row_st * RSTRIDE + half_st * 64) << 2);
                #pragma unroll
                for (int q = 0; q < 16; q++)
                    cp_async16(d32 + q * 16, erow + half_st * 16 + q);
                CP_COMMIT();
            };

            int b = 0;
            if (warp < nwin) stage(warp, 0);

            for (int w = warp; w < nwin; w += WPB) {
                int wn = w + WPB;
                if (wn < nwin) { stage(wn, b ^ 1); CP_WAIT(1); }
                else           { CP_WAIT(0); }
                __syncwarp();

                const float* A = mybuf0 + b * BUFFL;
                float c[8][4];
                #pragma unroll
                for (int nt = 0; nt < 8; nt++)
                    #pragma unroll
                    for (int p = 0; p < 4; p++) c[nt][p] = 0.f;

                #pragma unroll
                for (int kt = 0; kt < 16; kt++) {
                    int k8 = kt * 8;
                    uint32_t a0 = f2tf32(A[g * RSTRIDE + k8 + t4]);
                    uint32_t a1 = f2tf32(A[(g + 8) * RSTRIDE + k8 + t4]);
                    uint32_t a2 = f2tf32(A[g * RSTRIDE + k8 + t4 + 4]);
                    uint32_t a3 = f2tf32(A[(g + 8) * RSTRIDE + k8 + t4 + 4]);
                    const uint2* B2 = (const uint2*)s_bf + kt * 256 + lane;
                    #pragma unroll
                    for (int nt = 0; nt < 8; nt++) {
                        uint2 bb = B2[nt * 32];
                        mma_tf32(c[nt], a0, a1, a2, a3, bb.x, bb.y);
                    }
                }

                // epilogue: lane holds src elem g at (c[nt][0],c[nt][1]),
                // dst elem g at (c[nt][2],c[nt][3]), cols nt*8 + 2*t4 (+1)
                float ss = 0.f, dd = 0.f;
                #pragma unroll
                for (int nt = 0; nt < 8; nt++) {
                    ss += c[nt][0]*c[nt][0] + c[nt][1]*c[nt][1];
                    dd += c[nt][2]*c[nt][2] + c[nt][3]*c[nt][3];
                }
                #pragma unroll
                for (int o = 2; o > 0; o >>= 1) {
                    ss += __shfl_xor_sync(qmask, ss, o);
                    dd += __shfl_xor_sync(qmask, dd, o);
                }
                float inv_s = 1.f / fmaxf(sqrtf(ss), 1e-12f);
                float inv_d = 1.f / fmaxf(sqrtf(dd), 1e-12f);

                float sc = 0.f;
                #pragma unroll
                for (int nt = 0; nt < 8; nt++) {
                    float d0 = c[nt][0] * inv_s + rv[nt].x - c[nt][2] * inv_d;
                    float d1 = c[nt][1] * inv_s + rv[nt].y - c[nt][3] * inv_d;
                    sc += d0 * d0 + d1 * d1;
                }
                #pragma unroll
                for (int o = 2; o > 0; o >>= 1)
                    sc += __shfl_xor_sync(qmask, sc, o);

                if (t4 == 0) {
                    int oi = s_wi[warp][b][g];
                    if (oi >= 0) out[oi] = sqrtf(sc);
                }
                b ^= 1;
            }
        }
        __syncthreads();
    }
}

// ---------- launch ----------
extern "C" void kernel_launch(void* const* d_in, const int* in_sizes, int n_in,
                              void* d_out, int out_size) {
    const int*   src = (const int*)d_in[0];
    const int*   rel = (const int*)d_in[1];
    const int*   dst = (const int*)d_in[2];
    const float* ent = (const float*)d_in[3];
    const float* rle = (const float*)d_in[4];
    const float* prj = (const float*)d_in[5];
    float*       out = (float*)d_out;

    int B = in_sizes[0];

    const int SMEM_BYTES = (BFRAGS + WPB * 2 * BUFFL) * 4;  // 32768+67584=100352
    cudaFuncSetAttribute(k_compute, cudaFuncAttributeMaxDynamicSharedMemorySize,
                         SMEM_BYTES);

    int gS = (B + 256 * 4 - 1) / (256 * 4);   // 64 blocks

    k_scatter<<<gS, 256>>>(rel, B);
    k_plan<<<1, NRMAX>>>();
    k_compute<<<GRID_C, TPB, SMEM_BYTES>>>(src, dst, ent, rle, prj, out);
}